// round 16
// baseline (speedup 1.0000x reference)
#include <cuda_runtime.h>
#include <cstdint>

#define BATCH 2
#define SEQ   2048
#define CH    1024
#define NH    16
#define HSZ   64
#define MTOT  (BATCH*SEQ)     // 4096
#define QSCALE 0.18033688011112042f   // 0.125 * log2(e): softmax in log2 domain
#define SK    36              // GEMM smem row stride (floats) -> conflict-free frags

// Scratch: device globals (no cudaMalloc allowed)
static __device__ float g_q[(size_t)BATCH*NH*SEQ*HSZ];
static __device__ float g_k[(size_t)BATCH*NH*SEQ*HSZ];
static __device__ float g_v[(size_t)BATCH*NH*SEQ*HSZ];
static __device__ float g_attn[(size_t)MTOT*CH];
static __device__ float g_xr[(size_t)MTOT*CH];        // tf32-rounded x
static __device__ float g_wqkvr[(size_t)3*CH*CH];     // tf32-rounded w_qkv
static __device__ float g_woutr[(size_t)CH*CH];       // tf32-rounded w_out

static __device__ __forceinline__ uint32_t f2tf32(float v) {
    uint32_t r;
    asm("cvt.rna.tf32.f32 %0, %1;" : "=r"(r) : "f"(v));
    return r;
}

static __device__ __forceinline__ float ex2(float x) {
    float r;
    asm("ex2.approx.ftz.f32 %0, %1;" : "=f"(r) : "f"(x));
    return r;
}

static __device__ __forceinline__ uint32_t smem_u32(const void* p) {
    uint32_t a;
    asm("{ .reg .u64 t; cvta.to.shared.u64 t, %1; cvt.u32.u64 %0, t; }" : "=r"(a) : "l"(p));
    return a;
}

static __device__ __forceinline__ void cpa16(uint32_t dst, const float* src) {
    asm volatile("cp.async.cg.shared.global [%0], [%1], 16;" :: "r"(dst), "l"(src));
}
#define CP_COMMIT() asm volatile("cp.async.commit_group;" ::: "memory")
#define CP_WAIT0()  asm volatile("cp.async.wait_group 0;" ::: "memory")
#define CP_WAIT1()  asm volatile("cp.async.wait_group 1;" ::: "memory")

static __device__ __forceinline__ void mma8(float* c, const uint32_t* a,
                                            uint32_t b0, uint32_t b1) {
    asm volatile(
        "mma.sync.aligned.m16n8k8.row.col.f32.tf32.tf32.f32 "
        "{%0,%1,%2,%3},{%4,%5,%6,%7},{%8,%9},{%0,%1,%2,%3};"
        : "+f"(c[0]), "+f"(c[1]), "+f"(c[2]), "+f"(c[3])
        : "r"(a[0]), "r"(a[1]), "r"(a[2]), "r"(a[3]), "r"(b0), "r"(b1));
}

// ---------------------------------------------------------------------------
// Fused pre-pass: round x, w_qkv, w_out fp32 -> tf32 (rna) in ONE launch.
// ---------------------------------------------------------------------------
#define N4_X    (MTOT*CH/4)            // 1048576
#define N4_WQKV (3*CH*CH/4)            // 786432
#define N4_WOUT (CH*CH/4)              // 262144
#define N4_ALL  (N4_X + N4_WQKV + N4_WOUT)
__global__ void round_all(const float* __restrict__ x, const float* __restrict__ wq,
                          const float* __restrict__ wo) {
    int i = blockIdx.x * blockDim.x + threadIdx.x;
    int stride = gridDim.x * blockDim.x;
    for (; i < N4_ALL; i += stride) {
        const float* src; float* dst; int j;
        if (i < N4_X)                 { src = x;  dst = g_xr;    j = i; }
        else if (i < N4_X + N4_WQKV)  { src = wq; dst = g_wqkvr; j = i - N4_X; }
        else                          { src = wo; dst = g_woutr; j = i - N4_X - N4_WQKV; }
        float4 v = ((const float4*)src)[j];
        uint4 o = make_uint4(f2tf32(v.x), f2tf32(v.y), f2tf32(v.z), f2tf32(v.w));
        ((uint4*)dst)[j] = o;
    }
}

// ---------------------------------------------------------------------------
// QKV GEMM (tf32 mma.sync): D[128x192] = xr[128,1024] . w_qkvr^T (one head).
// Warp tile 32x96 -> 96 MMAs per chunk per warp (2x barrier amortization).
// 2-stage cp.async pipeline. Epilogue de-interleaves the head's q/k/v.
// ---------------------------------------------------------------------------
#define QKV_SMEM (128*196*4)   // 100352 B (epilogue Ds; > pipeline's 92160)
__global__ __launch_bounds__(256, 2) void qkv_tc() {
    extern __shared__ __align__(16) float sm[];
    const uint32_t sbase = smem_u32(sm);
    uint32_t* sAu = (uint32_t*)sm;                 // 2 bufs x 128*SK
    uint32_t* sBu = (uint32_t*)sm + 2 * 128 * SK;  // 2 bufs x 192*SK
    const float* A = g_xr;
    const float* W = g_wqkvr;

    const int tid = threadIdx.x, warp = tid >> 5, lane = tid & 31;
    const int wm = warp >> 1, wn = warp & 1;
    const int g = lane >> 2, t = lane & 3;
    const int m0 = blockIdx.y * 128;
    const int bx = blockIdx.x;          // head index 0..15
    const int n0 = bx * 192;

    float acc[2][12][4];
#pragma unroll
    for (int i = 0; i < 2; ++i)
#pragma unroll
        for (int j = 0; j < 12; ++j)
#pragma unroll
            for (int q = 0; q < 4; ++q) acc[i][j][q] = 0.f;

    auto CPAB = [&](int c, int buf) {
        const int k0 = 32 * c;
        const uint32_t ao = sbase + (uint32_t)(buf * 128 * SK * 4);
        const uint32_t bo = sbase + (uint32_t)((2 * 128 + buf * 192) * SK * 4);
#pragma unroll
        for (int p = 0; p < 4; ++p) {
            int idx = tid + 256 * p, r = idx >> 3, q = idx & 7;
            cpa16(ao + (uint32_t)((r * SK + 4 * q) * 4),
                  A + (size_t)(m0 + r) * CH + k0 + 4 * q);
        }
#pragma unroll
        for (int p = 0; p < 6; ++p) {
            int idx = tid + 256 * p, r = idx >> 3, q = idx & 7;
            cpa16(bo + (uint32_t)((r * SK + 4 * q) * 4),
                  W + (size_t)(n0 + r) * CH + k0 + 4 * q);
        }
        CP_COMMIT();
    };

    CPAB(0, 0);

    for (int c = 0; c < 32; ++c) {
        const int buf = c & 1;
        CP_WAIT0();
        __syncthreads();   // chunk c landed; all warps done with buf (chunk c-2)
        if (c < 31) CPAB(c + 1, buf ^ 1);

        const uint32_t* bA = sAu + buf * 128 * SK;
        const uint32_t* bB = sBu + buf * 192 * SK;
#pragma unroll
        for (int s = 0; s < 4; ++s) {
            uint32_t afr[2][4];
#pragma unroll
            for (int mi = 0; mi < 2; ++mi) {
                const uint32_t* pa = bA + (wm * 32 + mi * 16 + g) * SK + s * 8 + t;
                afr[mi][0] = pa[0];
                afr[mi][1] = pa[8 * SK];
                afr[mi][2] = pa[4];
                afr[mi][3] = pa[8 * SK + 4];
            }
#pragma unroll
            for (int nj = 0; nj < 12; ++nj) {
                const uint32_t* pb = bB + (wn * 96 + nj * 8 + g) * SK + s * 8 + t;
                uint32_t b0 = pb[0], b1 = pb[4];
                mma8(acc[0][nj], afr[0], b0, b1);
                mma8(acc[1][nj], afr[1], b0, b1);
            }
        }
    }
    __syncthreads();   // all compute done before smem reuse for Ds

    float* Ds = sm;    // [128][196]
#pragma unroll
    for (int mi = 0; mi < 2; ++mi)
#pragma unroll
        for (int nj = 0; nj < 12; ++nj) {
            int row = wm * 32 + mi * 16 + g;
            int col = wn * 96 + nj * 8 + 2 * t;
            *(float2*)(Ds + row * 196 + col) =
                make_float2(acc[mi][nj][0], acc[mi][nj][1]);
            *(float2*)(Ds + (row + 8) * 196 + col) =
                make_float2(acc[mi][nj][2], acc[mi][nj][3]);
        }
    __syncthreads();

    const int h = bx;
#pragma unroll
    for (int p = 0; p < 24; ++p) {
        int id = tid + 256 * p;       // 128 rows x 3 s x 16 c4-groups = 6144
        int c4 = id & 15;
        int s = (id >> 4) % 3;
        int row = id / 48;
        int m = m0 + row;
        int bb = m >> 11, nn = m & 2047;
        float* dst = (s == 0) ? g_q : (s == 1) ? g_k : g_v;
        const float* Dr = Ds + row * 196 + 12 * c4 + s;
        float4 o;
        o.x = __uint_as_float(f2tf32(Dr[0]));
        o.y = __uint_as_float(f2tf32(Dr[3]));
        o.z = __uint_as_float(f2tf32(Dr[6]));
        o.w = __uint_as_float(f2tf32(Dr[9]));
        *(float4*)(dst + ((size_t)(bb * NH + h) * SEQ + nn) * HSZ + 4 * c4) = o;
    }
}

// ---------------------------------------------------------------------------
// Flash attention (tf32 mma.sync): verified round-15 version (unchanged).
// ---------------------------------------------------------------------------
#define KSTR 68
#define VSTR 72
#define VBASE (2*64*KSTR)                    // 8704 (words)
#define PBASE (VBASE + 2*64*VSTR)            // 17920 (words)
#define ATTN_SMEM ((PBASE + 128*KSTR) * 4)   // 106496 B
__global__ __launch_bounds__(256, 2) void attn_tc() {
    extern __shared__ __align__(16) float sm[];
    uint32_t* Ks = (uint32_t*)sm;
    uint32_t* Vs = (uint32_t*)sm + VBASE;
    uint32_t* Ps = (uint32_t*)sm + PBASE;
    const uint32_t sbase = smem_u32(sm);

    const int tid = threadIdx.x, warp = tid >> 5, lane = tid & 31;
    const int g = lane >> 2, t = lane & 3;
    const int bh = blockIdx.y;
    const int m0 = blockIdx.x * 128;
    const int wrow = warp * 16;
    const float* Qg = g_q + (size_t)bh * SEQ * HSZ;
    const float* Kg = g_k + (size_t)bh * SEQ * HSZ;
    const float* Vg = g_v + (size_t)bh * SEQ * HSZ;

    auto CPKV = [&](int n0, int b) {
#pragma unroll
        for (int p = 0; p < 4; ++p) {
            int idx = tid + 256 * p;
            int r = idx >> 4, q = idx & 15;
            cpa16(sbase + (uint32_t)(((b * 64 + r) * KSTR + 4 * q) * 4),
                  Kg + (size_t)(n0 + r) * HSZ + 4 * q);
            cpa16(sbase + (uint32_t)((VBASE + (b * 64 + r) * VSTR + 4 * q) * 4),
                  Vg + (size_t)(n0 + r) * HSZ + 4 * q);
        }
        CP_COMMIT();
    };

    uint32_t qfr[8][4];
    {
        const float* q0 = Qg + (size_t)(m0 + wrow + g) * HSZ;
        const float* q1 = Qg + (size_t)(m0 + wrow + g + 8) * HSZ;
#pragma unroll
        for (int ks = 0; ks < 8; ++ks) {
            int c0 = ks * 8 + t, c1 = c0 + 4;
            qfr[ks][0] = f2tf32(q0[c0] * QSCALE);
            qfr[ks][1] = f2tf32(q1[c0] * QSCALE);
            qfr[ks][2] = f2tf32(q0[c1] * QSCALE);
            qfr[ks][3] = f2tf32(q1[c1] * QSCALE);
        }
    }

    CPKV(0, 0);

    float m_i[2] = {-1e30f, -1e30f};
    float l_i[2] = {0.f, 0.f};
    float acc_o[8][4];
#pragma unroll
    for (int nj = 0; nj < 8; ++nj)
#pragma unroll
        for (int q = 0; q < 4; ++q) acc_o[nj][q] = 0.f;

    for (int kt = 0; kt < 32; ++kt) {
        const int b = kt & 1;
        CP_WAIT0();
        __syncthreads();
        if (kt < 31) CPKV(64 * (kt + 1), b ^ 1);

        const uint32_t* Kb = Ks + b * 64 * KSTR;
        const uint32_t* Vb = Vs + b * 64 * VSTR;

        float s[8][4];
#pragma unroll
        for (int nj = 0; nj < 8; ++nj)
#pragma unroll
            for (int q = 0; q < 4; ++q) s[nj][q] = 0.f;
#pragma unroll
        for (int ks = 0; ks < 8; ++ks) {
#pragma unroll
            for (int nj = 0; nj < 8; ++nj) {
                const uint32_t* pb = Kb + (nj * 8 + g) * KSTR + ks * 8 + t;
                mma8(s[nj], qfr[ks], pb[0], pb[4]);
            }
        }

        float mx0 = -1e30f, mx1 = -1e30f;
#pragma unroll
        for (int nj = 0; nj < 8; ++nj) {
            mx0 = fmaxf(mx0, fmaxf(s[nj][0], s[nj][1]));
            mx1 = fmaxf(mx1, fmaxf(s[nj][2], s[nj][3]));
        }
        mx0 = fmaxf(mx0, __shfl_xor_sync(0xffffffffu, mx0, 1));
        mx0 = fmaxf(mx0, __shfl_xor_sync(0xffffffffu, mx0, 2));
        mx1 = fmaxf(mx1, __shfl_xor_sync(0xffffffffu, mx1, 1));
        mx1 = fmaxf(mx1, __shfl_xor_sync(0xffffffffu, mx1, 2));
        float mn0 = fmaxf(m_i[0], mx0), mn1 = fmaxf(m_i[1], mx1);
        float a0 = ex2(m_i[0] - mn0), a1 = ex2(m_i[1] - mn1);
        m_i[0] = mn0; m_i[1] = mn1;
        float s0 = 0.f, s1 = 0.f;
#pragma unroll
        for (int nj = 0; nj < 8; ++nj) {
            s[nj][0] = ex2(s[nj][0] - mn0);
            s[nj][1] = ex2(s[nj][1] - mn0);
            s[nj][2] = ex2(s[nj][2] - mn1);
            s[nj][3] = ex2(s[nj][3] - mn1);
            s0 += s[nj][0] + s[nj][1];
            s1 += s[nj][2] + s[nj][3];
        }
        s0 += __shfl_xor_sync(0xffffffffu, s0, 1);
        s0 += __shfl_xor_sync(0xffffffffu, s0, 2);
        s1 += __shfl_xor_sync(0xffffffffu, s1, 1);
        s1 += __shfl_xor_sync(0xffffffffu, s1, 2);
        l_i[0] = l_i[0] * a0 + s0;
        l_i[1] = l_i[1] * a1 + s1;
#pragma unroll
        for (int nj = 0; nj < 8; ++nj) {
            acc_o[nj][0] *= a0; acc_o[nj][1] *= a0;
            acc_o[nj][2] *= a1; acc_o[nj][3] *= a1;
        }

        uint32_t* pr0 = Ps + (wrow + g) * KSTR + 2 * t;
        uint32_t* pr1 = Ps + (wrow + g + 8) * KSTR + 2 * t;
#pragma unroll
        for (int nj = 0; nj < 8; ++nj) {
            uint2 w0 = make_uint2(f2tf32(s[nj][0]), f2tf32(s[nj][1]));
            uint2 w1 = make_uint2(f2tf32(s[nj][2]), f2tf32(s[nj][3]));
            *(uint2*)(pr0 + nj * 8) = w0;
            *(uint2*)(pr1 + nj * 8) = w1;
        }
        __syncwarp();

#pragma unroll
        for (int ks = 0; ks < 8; ++ks) {
            uint32_t afr[4];
            const uint32_t* pa = Ps + (wrow + g) * KSTR + ks * 8 + t;
            afr[0] = pa[0];
            afr[1] = pa[8 * KSTR];
            afr[2] = pa[4];
            afr[3] = pa[8 * KSTR + 4];
            const uint32_t* vb0 = Vb + (ks * 8 + t) * VSTR + g;
            const uint32_t* vb1 = Vb + (ks * 8 + t + 4) * VSTR + g;
#pragma unroll
            for (int nj = 0; nj < 8; ++nj)
                mma8(acc_o[nj], afr, vb0[nj * 8], vb1[nj * 8]);
        }
        __syncwarp();
    }

    const int b = bh >> 4, h = bh & 15;
    const float inv0 = 1.f / l_i[0], inv1 = 1.f / l_i[1];
    const int r0 = m0 + wrow + g, r1 = r0 + 8;
#pragma unroll
    for (int nj = 0; nj < 8; ++nj) {
        int col = h * HSZ + nj * 8 + 2 * t;
        float2 o0 = make_float2(__uint_as_float(f2tf32(acc_o[nj][0] * inv0)),
                                __uint_as_float(f2tf32(acc_o[nj][1] * inv0)));
        float2 o1 = make_float2(__uint_as_float(f2tf32(acc_o[nj][2] * inv1)),
                                __uint_as_float(f2tf32(acc_o[nj][3] * inv1)));
        *(float2*)(g_attn + ((size_t)(b * SEQ + r0)) * CH + col) = o0;
        *(float2*)(g_attn + ((size_t)(b * SEQ + r1)) * CH + col) = o1;
    }
}

// ---------------------------------------------------------------------------
// Output projection (tf32 mma.sync): out[128x128] = g_attn . w_outr^T + bias
// Pre-rounded inputs, 3-stage cp.async pipeline (verified round-14 version).
// ---------------------------------------------------------------------------
#define PROJ_SMEM (3*2*128*SK*4)   // 110592 B
__global__ __launch_bounds__(256, 2) void proj_tc(const float* __restrict__ bias,
                                                  float* __restrict__ out) {
    extern __shared__ __align__(16) float sm[];
    const uint32_t sbase = smem_u32(sm);
    uint32_t* sAu = (uint32_t*)sm;
    uint32_t* sBu = (uint32_t*)sm + 3 * 128 * SK;
    const float* W = g_woutr;

    const int tid = threadIdx.x, warp = tid >> 5, lane = tid & 31;
    const int wm = warp >> 1, wn = warp & 1;
    const int g = lane >> 2, t = lane & 3;
    const int m0 = blockIdx.y * 128;
    const int n0 = blockIdx.x * 128;

    float acc[2][8][4];
#pragma unroll
    for (int i = 0; i < 2; ++i)
#pragma unroll
        for (int j = 0; j < 8; ++j)
#pragma unroll
            for (int q = 0; q < 4; ++q) acc[i][j][q] = 0.f;

    auto CPAB = [&](int c, int buf) {
        const int k0 = 32 * c;
        const uint32_t ao = sbase + (uint32_t)(buf * 128 * SK * 4);
        const uint32_t bo = sbase + (uint32_t)((3 + buf) * 128 * SK * 4);
#pragma unroll
        for (int p = 0; p < 4; ++p) {
            int idx = tid + 256 * p, r = idx >> 3, q = idx & 7;
            cpa16(ao + (uint32_t)((r * SK + 4 * q) * 4),
                  g_attn + (size_t)(m0 + r) * CH + k0 + 4 * q);
            cpa16(bo + (uint32_t)((r * SK + 4 * q) * 4),
                  W + (size_t)(n0 + r) * CH + k0 + 4 * q);
        }
        CP_COMMIT();
    };

    CPAB(0, 0);
    CPAB(1, 1);

    for (int c = 0; c < 32; ++c) {
        const int buf = c % 3;
        if (c == 31) CP_WAIT0(); else CP_WAIT1();
        __syncthreads();
        if (c < 30) CPAB(c + 2, (c + 2) % 3);

        const uint32_t* bA = sAu + buf * 128 * SK;
        const uint32_t* bB = sBu + buf * 128 * SK;
#pragma unroll
        for (int s = 0; s < 4; ++s) {
            uint32_t afr[2][4];
#pragma unroll
            for (int mi = 0; mi < 2; ++mi) {
                const uint32_t* pa = bA + (wm * 32 + mi * 16 + g) * SK + s * 8 + t;
                afr[mi][0] = pa[0];
                afr[mi][1] = pa[8 * SK];
                afr[mi][2] = pa[4];
                afr[mi][3] = pa[8 * SK + 4];
            }
#pragma unroll
            for (int nj = 0; nj < 8; ++nj) {
                const uint32_t* pb = bB + (wn * 64 + nj * 8 + g) * SK + s * 8 + t;
                uint32_t b0 = pb[0], b1 = pb[4];
                mma8(acc[0][nj], afr[0], b0, b1);
                mma8(acc[1][nj], afr[1], b0, b1);
            }
        }
    }

#pragma unroll
    for (int mi = 0; mi < 2; ++mi)
#pragma unroll
        for (int nj = 0; nj < 8; ++nj) {
            int row = m0 + wm * 32 + mi * 16 + g;
            int col = n0 + wn * 64 + nj * 8 + 2 * t;
            float b0 = __ldg(bias + col), b1 = __ldg(bias + col + 1);
            *(float2*)(out + (size_t)row * CH + col) =
                make_float2(acc[mi][nj][0] + b0, acc[mi][nj][1] + b1);
            *(float2*)(out + (size_t)(row + 8) * CH + col) =
                make_float2(acc[mi][nj][2] + b0, acc[mi][nj][3] + b1);
        }
}

extern "C" void kernel_launch(void* const* d_in, const int* in_sizes, int n_in,
                              void* d_out, int out_size) {
    const float* x     = (const float*)d_in[0];
    const float* w_qkv = (const float*)d_in[1];
    const float* w_out = (const float*)d_in[2];
    const float* b_out = (const float*)d_in[3];
    float* out = (float*)d_out;

    cudaFuncSetAttribute(qkv_tc, cudaFuncAttributeMaxDynamicSharedMemorySize, QKV_SMEM);
    cudaFuncSetAttribute(attn_tc, cudaFuncAttributeMaxDynamicSharedMemorySize, ATTN_SMEM);
    cudaFuncSetAttribute(proj_tc, cudaFuncAttributeMaxDynamicSharedMemorySize, PROJ_SMEM);

    round_all<<<2368, 256>>>(x, w_qkv, w_out);
    qkv_tc<<<dim3(NH, 32), 256, QKV_SMEM>>>();
    attn_tc<<<dim3(SEQ / 128, BATCH * NH), 256, ATTN_SMEM>>>();
    proj_tc<<<dim3(CH / 128, MTOT / 128), 256, PROJ_SMEM>>>(b_out, out);
}

// round 17
// speedup vs baseline: 1.0147x; 1.0147x over previous
#include <cuda_runtime.h>
#include <cstdint>

#define BATCH 2
#define SEQ   2048
#define CH    1024
#define NH    16
#define HSZ   64
#define MTOT  (BATCH*SEQ)     // 4096
#define QSCALE 0.18033688011112042f   // 0.125 * log2(e): softmax in log2 domain
#define SK    36              // GEMM smem row stride (floats) -> conflict-free frags

// Scratch: device globals (no cudaMalloc allowed)
static __device__ float g_q[(size_t)BATCH*NH*SEQ*HSZ];
static __device__ float g_k[(size_t)BATCH*NH*SEQ*HSZ];
static __device__ float g_v[(size_t)BATCH*NH*SEQ*HSZ];
static __device__ float g_attn[(size_t)MTOT*CH];
static __device__ float g_xr[(size_t)MTOT*CH];        // tf32-rounded x
static __device__ float g_wqkvr[(size_t)3*CH*CH];     // tf32-rounded w_qkv
static __device__ float g_woutr[(size_t)CH*CH];       // tf32-rounded w_out

static __device__ __forceinline__ uint32_t f2tf32(float v) {
    uint32_t r;
    asm("cvt.rna.tf32.f32 %0, %1;" : "=r"(r) : "f"(v));
    return r;
}

static __device__ __forceinline__ float ex2(float x) {
    float r;
    asm("ex2.approx.ftz.f32 %0, %1;" : "=f"(r) : "f"(x));
    return r;
}

static __device__ __forceinline__ uint32_t smem_u32(const void* p) {
    uint32_t a;
    asm("{ .reg .u64 t; cvta.to.shared.u64 t, %1; cvt.u32.u64 %0, t; }" : "=r"(a) : "l"(p));
    return a;
}

static __device__ __forceinline__ void cpa16(uint32_t dst, const float* src) {
    asm volatile("cp.async.cg.shared.global [%0], [%1], 16;" :: "r"(dst), "l"(src));
}
#define CP_COMMIT() asm volatile("cp.async.commit_group;" ::: "memory")
#define CP_WAIT0()  asm volatile("cp.async.wait_group 0;" ::: "memory")
#define CP_WAIT1()  asm volatile("cp.async.wait_group 1;" ::: "memory")

static __device__ __forceinline__ void mma8(float* c, const uint32_t* a,
                                            uint32_t b0, uint32_t b1) {
    asm volatile(
        "mma.sync.aligned.m16n8k8.row.col.f32.tf32.tf32.f32 "
        "{%0,%1,%2,%3},{%4,%5,%6,%7},{%8,%9},{%0,%1,%2,%3};"
        : "+f"(c[0]), "+f"(c[1]), "+f"(c[2]), "+f"(c[3])
        : "r"(a[0]), "r"(a[1]), "r"(a[2]), "r"(a[3]), "r"(b0), "r"(b1));
}

// ---------------------------------------------------------------------------
// Pre-pass: round fp32 -> tf32 (rna). Grid statically partitioned by segment
// so each block's src/dst are loop-invariant (clean LDG/STG streams).
// Blocks: [0,1184) -> x, [1184,2072) -> w_qkv, [2072,2368) -> w_out.
// ---------------------------------------------------------------------------
#define N4_X    (MTOT*CH/4)            // 1048576
#define N4_WQKV (3*CH*CH/4)            // 786432
#define N4_WOUT (CH*CH/4)              // 262144
#define PB_X    1184
#define PB_WQ   888
#define PB_WO   296
__global__ void round_all(const float* __restrict__ x, const float* __restrict__ wq,
                          const float* __restrict__ wo) {
    const float* src; float* dst; int n4, b0, nb;
    if (blockIdx.x < PB_X)              { src = x;  dst = g_xr;    n4 = N4_X;    b0 = 0;             nb = PB_X;  }
    else if (blockIdx.x < PB_X + PB_WQ) { src = wq; dst = g_wqkvr; n4 = N4_WQKV; b0 = PB_X;          nb = PB_WQ; }
    else                                { src = wo; dst = g_woutr; n4 = N4_WOUT; b0 = PB_X + PB_WQ;  nb = PB_WO; }
    int i = (blockIdx.x - b0) * blockDim.x + threadIdx.x;
    int stride = nb * blockDim.x;
    for (; i < n4; i += stride) {
        float4 v = ((const float4*)src)[i];
        uint4 o = make_uint4(f2tf32(v.x), f2tf32(v.y), f2tf32(v.z), f2tf32(v.w));
        ((uint4*)dst)[i] = o;
    }
}

// ---------------------------------------------------------------------------
// QKV GEMM (tf32 mma.sync): D[128x96] = xr[128,1024] . w_qkvr^T slice
// Pre-rounded inputs, 3-stage cp.async pipeline (verified round-15 version).
// ---------------------------------------------------------------------------
#define QKV_SMEM (3*(128+96)*SK*4)   // 96768 B
__global__ __launch_bounds__(256, 2) void qkv_tc() {
    extern __shared__ __align__(16) float sm[];
    const uint32_t sbase = smem_u32(sm);
    uint32_t* sAu = (uint32_t*)sm;                 // 3 bufs x 128*SK
    uint32_t* sBu = (uint32_t*)sm + 3 * 128 * SK;  // 3 bufs x 96*SK
    const float* A = g_xr;
    const float* W = g_wqkvr;

    const int tid = threadIdx.x, warp = tid >> 5, lane = tid & 31;
    const int wm = warp >> 1, wn = warp & 1;
    const int g = lane >> 2, t = lane & 3;
    const int m0 = blockIdx.y * 128;
    const int bx = blockIdx.x;
    const int n0 = bx * 96;

    float acc[2][6][4];
#pragma unroll
    for (int i = 0; i < 2; ++i)
#pragma unroll
        for (int j = 0; j < 6; ++j)
#pragma unroll
            for (int q = 0; q < 4; ++q) acc[i][j][q] = 0.f;

    auto CPAB = [&](int c, int buf) {
        const int k0 = 32 * c;
        const uint32_t ao = sbase + (uint32_t)(buf * 128 * SK * 4);
        const uint32_t bo = sbase + (uint32_t)((3 * 128 + buf * 96) * SK * 4);
#pragma unroll
        for (int p = 0; p < 4; ++p) {
            int idx = tid + 256 * p, r = idx >> 3, q = idx & 7;
            cpa16(ao + (uint32_t)((r * SK + 4 * q) * 4),
                  A + (size_t)(m0 + r) * CH + k0 + 4 * q);
        }
#pragma unroll
        for (int p = 0; p < 3; ++p) {
            int idx = tid + 256 * p, r = idx >> 3, q = idx & 7;
            cpa16(bo + (uint32_t)((r * SK + 4 * q) * 4),
                  W + (size_t)(n0 + r) * CH + k0 + 4 * q);
        }
        CP_COMMIT();
    };

    CPAB(0, 0);
    CPAB(1, 1);

    for (int c = 0; c < 32; ++c) {
        const int buf = c % 3;
        if (c == 31) CP_WAIT0(); else CP_WAIT1();   // chunk c resident
        __syncthreads();    // all warps past chunk c-1 reads -> buf (c+2)%3 reusable
        if (c < 30) CPAB(c + 2, (c + 2) % 3);

        const uint32_t* bA = sAu + buf * 128 * SK;
        const uint32_t* bB = sBu + buf * 96 * SK;
#pragma unroll
        for (int s = 0; s < 4; ++s) {
            uint32_t afr[2][4];
#pragma unroll
            for (int mi = 0; mi < 2; ++mi) {
                const uint32_t* pa = bA + (wm * 32 + mi * 16 + g) * SK + s * 8 + t;
                afr[mi][0] = pa[0];
                afr[mi][1] = pa[8 * SK];
                afr[mi][2] = pa[4];
                afr[mi][3] = pa[8 * SK + 4];
            }
#pragma unroll
            for (int nj = 0; nj < 6; ++nj) {
                const uint32_t* pb = bB + (wn * 48 + nj * 8 + g) * SK + s * 8 + t;
                uint32_t b0 = pb[0], b1 = pb[4];
                mma8(acc[0][nj], afr[0], b0, b1);
                mma8(acc[1][nj], afr[1], b0, b1);
            }
        }
    }
    __syncthreads();   // all compute done before smem reuse for Ds

    float* Ds = sm;
#pragma unroll
    for (int mi = 0; mi < 2; ++mi)
#pragma unroll
        for (int nj = 0; nj < 6; ++nj) {
            int row = wm * 32 + mi * 16 + g;
            int col = wn * 48 + nj * 8 + 2 * t;
            *(float2*)(Ds + row * 100 + col) =
                make_float2(acc[mi][nj][0], acc[mi][nj][1]);
            *(float2*)(Ds + (row + 8) * 100 + col) =
                make_float2(acc[mi][nj][2], acc[mi][nj][3]);
        }
    __syncthreads();

    const int h = bx >> 1, hs0 = (bx & 1) * 32;
#pragma unroll
    for (int p = 0; p < 12; ++p) {
        int id = tid + 256 * p;
        int c4 = id & 7;
        int s = (id >> 3) % 3;
        int row = id / 24;
        int m = m0 + row;
        int bb = m >> 11, nn = m & 2047;
        float* dst = (s == 0) ? g_q : (s == 1) ? g_k : g_v;
        const float* Dr = Ds + row * 100 + 12 * c4 + s;
        float4 o;
        o.x = __uint_as_float(f2tf32(Dr[0]));
        o.y = __uint_as_float(f2tf32(Dr[3]));
        o.z = __uint_as_float(f2tf32(Dr[6]));
        o.w = __uint_as_float(f2tf32(Dr[9]));
        *(float4*)(dst + ((size_t)(bb * NH + h) * SEQ + nn) * HSZ + hs0 + 4 * c4) = o;
    }
}

// ---------------------------------------------------------------------------
// Flash attention (tf32 mma.sync): verified round-15 version (unchanged).
// K stride 68, V stride 72 (conflict-free), P stride 68, MUFU ex2.
// ---------------------------------------------------------------------------
#define KSTR 68
#define VSTR 72
#define VBASE (2*64*KSTR)                    // 8704 (words)
#define PBASE (VBASE + 2*64*VSTR)            // 17920 (words)
#define ATTN_SMEM ((PBASE + 128*KSTR) * 4)   // 106496 B
__global__ __launch_bounds__(256, 2) void attn_tc() {
    extern __shared__ __align__(16) float sm[];
    uint32_t* Ks = (uint32_t*)sm;
    uint32_t* Vs = (uint32_t*)sm + VBASE;
    uint32_t* Ps = (uint32_t*)sm + PBASE;
    const uint32_t sbase = smem_u32(sm);

    const int tid = threadIdx.x, warp = tid >> 5, lane = tid & 31;
    const int g = lane >> 2, t = lane & 3;
    const int bh = blockIdx.y;
    const int m0 = blockIdx.x * 128;
    const int wrow = warp * 16;
    const float* Qg = g_q + (size_t)bh * SEQ * HSZ;
    const float* Kg = g_k + (size_t)bh * SEQ * HSZ;
    const float* Vg = g_v + (size_t)bh * SEQ * HSZ;

    auto CPKV = [&](int n0, int b) {
#pragma unroll
        for (int p = 0; p < 4; ++p) {
            int idx = tid + 256 * p;
            int r = idx >> 4, q = idx & 15;
            cpa16(sbase + (uint32_t)(((b * 64 + r) * KSTR + 4 * q) * 4),
                  Kg + (size_t)(n0 + r) * HSZ + 4 * q);
            cpa16(sbase + (uint32_t)((VBASE + (b * 64 + r) * VSTR + 4 * q) * 4),
                  Vg + (size_t)(n0 + r) * HSZ + 4 * q);
        }
        CP_COMMIT();
    };

    uint32_t qfr[8][4];
    {
        const float* q0 = Qg + (size_t)(m0 + wrow + g) * HSZ;
        const float* q1 = Qg + (size_t)(m0 + wrow + g + 8) * HSZ;
#pragma unroll
        for (int ks = 0; ks < 8; ++ks) {
            int c0 = ks * 8 + t, c1 = c0 + 4;
            qfr[ks][0] = f2tf32(q0[c0] * QSCALE);
            qfr[ks][1] = f2tf32(q1[c0] * QSCALE);
            qfr[ks][2] = f2tf32(q0[c1] * QSCALE);
            qfr[ks][3] = f2tf32(q1[c1] * QSCALE);
        }
    }

    CPKV(0, 0);

    float m_i[2] = {-1e30f, -1e30f};
    float l_i[2] = {0.f, 0.f};
    float acc_o[8][4];
#pragma unroll
    for (int nj = 0; nj < 8; ++nj)
#pragma unroll
        for (int q = 0; q < 4; ++q) acc_o[nj][q] = 0.f;

    for (int kt = 0; kt < 32; ++kt) {
        const int b = kt & 1;
        CP_WAIT0();
        __syncthreads();
        if (kt < 31) CPKV(64 * (kt + 1), b ^ 1);

        const uint32_t* Kb = Ks + b * 64 * KSTR;
        const uint32_t* Vb = Vs + b * 64 * VSTR;

        float s[8][4];
#pragma unroll
        for (int nj = 0; nj < 8; ++nj)
#pragma unroll
            for (int q = 0; q < 4; ++q) s[nj][q] = 0.f;
#pragma unroll
        for (int ks = 0; ks < 8; ++ks) {
#pragma unroll
            for (int nj = 0; nj < 8; ++nj) {
                const uint32_t* pb = Kb + (nj * 8 + g) * KSTR + ks * 8 + t;
                mma8(s[nj], qfr[ks], pb[0], pb[4]);
            }
        }

        float mx0 = -1e30f, mx1 = -1e30f;
#pragma unroll
        for (int nj = 0; nj < 8; ++nj) {
            mx0 = fmaxf(mx0, fmaxf(s[nj][0], s[nj][1]));
            mx1 = fmaxf(mx1, fmaxf(s[nj][2], s[nj][3]));
        }
        mx0 = fmaxf(mx0, __shfl_xor_sync(0xffffffffu, mx0, 1));
        mx0 = fmaxf(mx0, __shfl_xor_sync(0xffffffffu, mx0, 2));
        mx1 = fmaxf(mx1, __shfl_xor_sync(0xffffffffu, mx1, 1));
        mx1 = fmaxf(mx1, __shfl_xor_sync(0xffffffffu, mx1, 2));
        float mn0 = fmaxf(m_i[0], mx0), mn1 = fmaxf(m_i[1], mx1);
        float a0 = ex2(m_i[0] - mn0), a1 = ex2(m_i[1] - mn1);
        m_i[0] = mn0; m_i[1] = mn1;
        float s0 = 0.f, s1 = 0.f;
#pragma unroll
        for (int nj = 0; nj < 8; ++nj) {
            s[nj][0] = ex2(s[nj][0] - mn0);
            s[nj][1] = ex2(s[nj][1] - mn0);
            s[nj][2] = ex2(s[nj][2] - mn1);
            s[nj][3] = ex2(s[nj][3] - mn1);
            s0 += s[nj][0] + s[nj][1];
            s1 += s[nj][2] + s[nj][3];
        }
        s0 += __shfl_xor_sync(0xffffffffu, s0, 1);
        s0 += __shfl_xor_sync(0xffffffffu, s0, 2);
        s1 += __shfl_xor_sync(0xffffffffu, s1, 1);
        s1 += __shfl_xor_sync(0xffffffffu, s1, 2);
        l_i[0] = l_i[0] * a0 + s0;
        l_i[1] = l_i[1] * a1 + s1;
#pragma unroll
        for (int nj = 0; nj < 8; ++nj) {
            acc_o[nj][0] *= a0; acc_o[nj][1] *= a0;
            acc_o[nj][2] *= a1; acc_o[nj][3] *= a1;
        }

        uint32_t* pr0 = Ps + (wrow + g) * KSTR + 2 * t;
        uint32_t* pr1 = Ps + (wrow + g + 8) * KSTR + 2 * t;
#pragma unroll
        for (int nj = 0; nj < 8; ++nj) {
            uint2 w0 = make_uint2(f2tf32(s[nj][0]), f2tf32(s[nj][1]));
            uint2 w1 = make_uint2(f2tf32(s[nj][2]), f2tf32(s[nj][3]));
            *(uint2*)(pr0 + nj * 8) = w0;
            *(uint2*)(pr1 + nj * 8) = w1;
        }
        __syncwarp();

#pragma unroll
        for (int ks = 0; ks < 8; ++ks) {
            uint32_t afr[4];
            const uint32_t* pa = Ps + (wrow + g) * KSTR + ks * 8 + t;
            afr[0] = pa[0];
            afr[1] = pa[8 * KSTR];
            afr[2] = pa[4];
            afr[3] = pa[8 * KSTR + 4];
            const uint32_t* vb0 = Vb + (ks * 8 + t) * VSTR + g;
            const uint32_t* vb1 = Vb + (ks * 8 + t + 4) * VSTR + g;
#pragma unroll
            for (int nj = 0; nj < 8; ++nj)
                mma8(acc_o[nj], afr, vb0[nj * 8], vb1[nj * 8]);
        }
        __syncwarp();
    }

    const int b = bh >> 4, h = bh & 15;
    const float inv0 = 1.f / l_i[0], inv1 = 1.f / l_i[1];
    const int r0 = m0 + wrow + g, r1 = r0 + 8;
#pragma unroll
    for (int nj = 0; nj < 8; ++nj) {
        int col = h * HSZ + nj * 8 + 2 * t;
        float2 o0 = make_float2(__uint_as_float(f2tf32(acc_o[nj][0] * inv0)),
                                __uint_as_float(f2tf32(acc_o[nj][1] * inv0)));
        float2 o1 = make_float2(__uint_as_float(f2tf32(acc_o[nj][2] * inv1)),
                                __uint_as_float(f2tf32(acc_o[nj][3] * inv1)));
        *(float2*)(g_attn + ((size_t)(b * SEQ + r0)) * CH + col) = o0;
        *(float2*)(g_attn + ((size_t)(b * SEQ + r1)) * CH + col) = o1;
    }
}

// ---------------------------------------------------------------------------
// Output projection (tf32 mma.sync): out[128x128] = g_attn . w_outr^T + bias
// Pre-rounded inputs, 3-stage cp.async pipeline (verified round-14 version).
// ---------------------------------------------------------------------------
#define PROJ_SMEM (3*2*128*SK*4)   // 110592 B
__global__ __launch_bounds__(256, 2) void proj_tc(const float* __restrict__ bias,
                                                  float* __restrict__ out) {
    extern __shared__ __align__(16) float sm[];
    const uint32_t sbase = smem_u32(sm);
    uint32_t* sAu = (uint32_t*)sm;
    uint32_t* sBu = (uint32_t*)sm + 3 * 128 * SK;
    const float* W = g_woutr;

    const int tid = threadIdx.x, warp = tid >> 5, lane = tid & 31;
    const int wm = warp >> 1, wn = warp & 1;
    const int g = lane >> 2, t = lane & 3;
    const int m0 = blockIdx.y * 128;
    const int n0 = blockIdx.x * 128;

    float acc[2][8][4];
#pragma unroll
    for (int i = 0; i < 2; ++i)
#pragma unroll
        for (int j = 0; j < 8; ++j)
#pragma unroll
            for (int q = 0; q < 4; ++q) acc[i][j][q] = 0.f;

    auto CPAB = [&](int c, int buf) {
        const int k0 = 32 * c;
        const uint32_t ao = sbase + (uint32_t)(buf * 128 * SK * 4);
        const uint32_t bo = sbase + (uint32_t)((3 + buf) * 128 * SK * 4);
#pragma unroll
        for (int p = 0; p < 4; ++p) {
            int idx = tid + 256 * p, r = idx >> 3, q = idx & 7;
            cpa16(ao + (uint32_t)((r * SK + 4 * q) * 4),
                  g_attn + (size_t)(m0 + r) * CH + k0 + 4 * q);
            cpa16(bo + (uint32_t)((r * SK + 4 * q) * 4),
                  W + (size_t)(n0 + r) * CH + k0 + 4 * q);
        }
        CP_COMMIT();
    };

    CPAB(0, 0);
    CPAB(1, 1);

    for (int c = 0; c < 32; ++c) {
        const int buf = c % 3;
        if (c == 31) CP_WAIT0(); else CP_WAIT1();
        __syncthreads();
        if (c < 30) CPAB(c + 2, (c + 2) % 3);

        const uint32_t* bA = sAu + buf * 128 * SK;
        const uint32_t* bB = sBu + buf * 128 * SK;
#pragma unroll
        for (int s = 0; s < 4; ++s) {
            uint32_t afr[2][4];
#pragma unroll
            for (int mi = 0; mi < 2; ++mi) {
                const uint32_t* pa = bA + (wm * 32 + mi * 16 + g) * SK + s * 8 + t;
                afr[mi][0] = pa[0];
                afr[mi][1] = pa[8 * SK];
                afr[mi][2] = pa[4];
                afr[mi][3] = pa[8 * SK + 4];
            }
#pragma unroll
            for (int nj = 0; nj < 8; ++nj) {
                const uint32_t* pb = bB + (wn * 64 + nj * 8 + g) * SK + s * 8 + t;
                uint32_t b0 = pb[0], b1 = pb[4];
                mma8(acc[0][nj], afr[0], b0, b1);
                mma8(acc[1][nj], afr[1], b0, b1);
            }
        }
    }

#pragma unroll
    for (int mi = 0; mi < 2; ++mi)
#pragma unroll
        for (int nj = 0; nj < 8; ++nj) {
            int row = m0 + wm * 32 + mi * 16 + g;
            int col = n0 + wn * 64 + nj * 8 + 2 * t;
            float b0 = __ldg(bias + col), b1 = __ldg(bias + col + 1);
            *(float2*)(out + (size_t)row * CH + col) =
                make_float2(acc[mi][nj][0] + b0, acc[mi][nj][1] + b1);
            *(float2*)(out + (size_t)(row + 8) * CH + col) =
                make_float2(acc[mi][nj][2] + b0, acc[mi][nj][3] + b1);
        }
}

extern "C" void kernel_launch(void* const* d_in, const int* in_sizes, int n_in,
                              void* d_out, int out_size) {
    const float* x     = (const float*)d_in[0];
    const float* w_qkv = (const float*)d_in[1];
    const float* w_out = (const float*)d_in[2];
    const float* b_out = (const float*)d_in[3];
    float* out = (float*)d_out;

    cudaFuncSetAttribute(qkv_tc, cudaFuncAttributeMaxDynamicSharedMemorySize, QKV_SMEM);
    cudaFuncSetAttribute(attn_tc, cudaFuncAttributeMaxDynamicSharedMemorySize, ATTN_SMEM);
    cudaFuncSetAttribute(proj_tc, cudaFuncAttributeMaxDynamicSharedMemorySize, PROJ_SMEM);

    round_all<<<PB_X + PB_WQ + PB_WO, 256>>>(x, w_qkv, w_out);
    qkv_tc<<<dim3(32, 32), 256, QKV_SMEM>>>();
    attn_tc<<<dim3(SEQ / 128, BATCH * NH), 256, ATTN_SMEM>>>();
    proj_tc<<<dim3(CH / 128, MTOT / 128), 256, PROJ_SMEM>>>(b_out, out);
}